// round 3
// baseline (speedup 1.0000x reference)
#include <cuda_runtime.h>
#include <cstdint>

#define GS 96
#define CC 64              // 8*8 elements per block
#define B_DIM 64
#define THREADS 256
#define WARPS (THREADS / 32)
#define TI 6               // i-rows per CTA (96 / 6 = 16 CTAs per batch row)

// out[b][i][j][c][k]: out[...][c][0] = x[b][i][c], out[...][c][1] = x[b][j][c]
// Per (b,i,j): 128 floats, pair-interleaved (xi[0],xj[0],xi[1],xj[1],...)
__global__ __launch_bounds__(THREADS) void gcom_kernel(const float* __restrict__ x,
                                                       float* __restrict__ out) {
    const int blk = blockIdx.x;          // 0 .. 64*16-1
    const int b   = blk >> 4;            // / 16
    const int i0  = (blk & 15) * TI;     // first i handled by this CTA

    // Stage the whole batch row (96*64 floats = 24.5 KB) ONCE per CTA
    __shared__ float xs[GS * CC];
    {
        const float4* src = reinterpret_cast<const float4*>(x + (size_t)b * GS * CC);
        float4* dst = reinterpret_cast<float4*>(xs);
        #pragma unroll
        for (int t = threadIdx.x; t < GS * CC / 4; t += THREADS)
            dst[t] = __ldg(src + t);
    }
    __syncthreads();

    const int quad = threadIdx.x & 31;   // float4 index within a j-row (32*16B = 512B)
    const int wid  = threadIdx.x >> 5;   // warp id 0..7 -> j stride
    const float2* __restrict__ xs2 = reinterpret_cast<const float2*>(xs);

    #pragma unroll
    for (int ii = 0; ii < TI; ii++) {
        const int i = i0 + ii;
        const float2 xiv = xs2[i * 32 + quad];     // xi pair, constant over j
        float4* __restrict__ op =
            reinterpret_cast<float4*>(out) + ((size_t)b * GS + i) * GS * 32;

        #pragma unroll 4
        for (int j = wid; j < GS; j += WARPS) {
            const float2 xjv = xs2[j * 32 + quad];
            float4 v;
            v.x = xiv.x; v.y = xjv.x;
            v.z = xiv.y; v.w = xjv.y;
            __stcs(op + (size_t)j * 32 + quad, v); // streaming, evict-first
        }
    }
}

extern "C" void kernel_launch(void* const* d_in, const int* in_sizes, int n_in,
                              void* d_out, int out_size) {
    const float* x = (const float*)d_in[0];
    float* out = (float*)d_out;
    gcom_kernel<<<B_DIM * (GS / TI), THREADS>>>(x, out);
}

// round 4
// speedup vs baseline: 1.1586x; 1.1586x over previous
#include <cuda_runtime.h>
#include <cstdint>

#define GS 96
#define CC 64               // 8*8 elements per block
#define B_DIM 64
#define THREADS 128
#define WARPS (THREADS / 32) // 4
#define JSPLIT 2             // CTAs per (b,i); each handles GS/JSPLIT j-rows
#define JCH (GS / JSPLIT)    // 48

// out[b][i][j][c][k]: out[...][c][0] = x[b][i][c], out[...][c][1] = x[b][j][c]
// Per (b,i,j): 128 floats, pair-interleaved (xi[0],xj[0],xi[1],xj[1],...)
__global__ __launch_bounds__(THREADS) void gcom_kernel(const float* __restrict__ x,
                                                       float* __restrict__ out) {
    const int blk   = blockIdx.x;            // 0 .. 64*96*2-1
    const int chunk = blk & (JSPLIT - 1);    // which j-chunk
    const int bi    = blk >> 1;              // (b, i)
    const int b     = bi / GS;
    const int j0    = chunk * JCH;

    // Stage this CTA's j-chunk (48*64*4 = 12.25 KB) + xi (256 B)
    __shared__ float xs[JCH * CC];
    __shared__ float xi_s[CC];
    {
        const float4* src =
            reinterpret_cast<const float4*>(x + ((size_t)b * GS + j0) * CC);
        float4* dst = reinterpret_cast<float4*>(xs);
        #pragma unroll
        for (int t = threadIdx.x; t < JCH * CC / 4; t += THREADS)
            dst[t] = __ldg(src + t);
        if (threadIdx.x < CC / 4)
            reinterpret_cast<float4*>(xi_s)[threadIdx.x] =
                __ldg(reinterpret_cast<const float4*>(x + (size_t)bi * CC) + threadIdx.x);
    }
    __syncthreads();

    const int quad = threadIdx.x & 31;   // float4 index within a j-row (32*16B = 512B)
    const int wid  = threadIdx.x >> 5;   // warp id 0..3 -> j stride

    const float2 xiv = reinterpret_cast<const float2*>(xi_s)[quad];
    const float2* __restrict__ xs2 = reinterpret_cast<const float2*>(xs);

    float4* __restrict__ op =
        reinterpret_cast<float4*>(out) + ((size_t)bi * GS + j0) * 32;

    #pragma unroll 4
    for (int jj = wid; jj < JCH; jj += WARPS) {
        const float2 xjv = xs2[jj * 32 + quad];
        float4 v;
        v.x = xiv.x; v.y = xjv.x;
        v.z = xiv.y; v.w = xjv.y;
        __stcs(op + (size_t)jj * 32 + quad, v);  // streaming, evict-first
    }
}

extern "C" void kernel_launch(void* const* d_in, const int* in_sizes, int n_in,
                              void* d_out, int out_size) {
    const float* x = (const float*)d_in[0];
    float* out = (float*)d_out;
    gcom_kernel<<<B_DIM * GS * JSPLIT, THREADS>>>(x, out);
}